// round 2
// baseline (speedup 1.0000x reference)
#include <cuda_runtime.h>
#include <math.h>

#define NB 8
#define FH 120
#define FW 160
#define NPIX (FH*FW)
#define NSEM 16
#define NC 20
#define MS 480
#define MS2 (MS*MS)
#define TCH 18            // hp channels: 0=exp count, 1=agent count, 2..17=agent sem
#define VRD 100
#define CELLS (VRD*VRD)
#define RB 160            // max bbox side (worst case ~149)

// scratch (static device memory: allowed)
__device__ float g_hp[NB*TCH*CELLS];             // [b][c][100][100]
__device__ float g_rot[(size_t)NB*TCH*MS2];      // rotated image (valid only inside bbox)
__device__ int   g_bbox[NB][4];                  // imin, imax, jmin, jmax (inclusive)

// analytic bounding box of the rotated window support (conservative)
__global__ void k_bbox(const float* __restrict__ poses) {
    int b = threadIdx.x;
    if (b >= NB) return;
    float th = (90.0f - poses[b*3+2]) * 0.017453292519943295f;
    float ct = cosf(th), st = sinf(th);
    const float gxlo = 189.0f/239.5f - 1.0f, gxhi = 290.0f/239.5f - 1.0f;
    const float gylo = 239.0f/239.5f - 1.0f, gyhi = 340.0f/239.5f - 1.0f;
    float gxs[2] = {gxlo, gxhi}, gys[2] = {gylo, gyhi};
    float xmn = 1e9f, xmx = -1e9f, ymn = 1e9f, ymx = -1e9f;
    #pragma unroll
    for (int a = 0; a < 2; a++)
        #pragma unroll
        for (int c = 0; c < 2; c++) {
            float gx = gxs[a], gy = gys[c];
            float x =  ct*gx + st*gy;
            float y = -st*gx + ct*gy;
            xmn = fminf(xmn, x); xmx = fmaxf(xmx, x);
            ymn = fminf(ymn, y); ymx = fmaxf(ymx, y);
        }
    int jmn = (int)floorf((xmn + 1.0f)*240.0f - 0.5f) - 2;
    int jmx = (int)ceilf ((xmx + 1.0f)*240.0f - 0.5f) + 2;
    int imn = (int)floorf((ymn + 1.0f)*240.0f - 0.5f) - 2;
    int imx = (int)ceilf ((ymx + 1.0f)*240.0f - 0.5f) + 2;
    g_bbox[b][0] = max(imn, 0); g_bbox[b][1] = min(imx, MS-1);
    g_bbox[b][2] = max(jmn, 0); g_bbox[b][3] = min(jmx, MS-1);
}

// smem-aggregated splat: one block per (hp-channel, batch). 144 blocks ~ 148 SMs.
// Flush fully overwrites g_hp, so no zero-kernel is needed.
__global__ void __launch_bounds__(256, 1) k_splat(const float* __restrict__ obs, float f_cam) {
    __shared__ float acc[CELLS];                 // 40 KB
    int ch = blockIdx.x;                         // 0..17
    int b  = blockIdx.y;
    for (int i = threadIdx.x; i < CELLS; i += 256) acc[i] = 0.0f;
    __syncthreads();

    const float* ob = obs + (size_t)b*NC*NPIX;
    const float* fsrc = (ch >= 2) ? (ob + (size_t)(ch+2)*NPIX) : (const float*)0; // sem ch-2 -> obs ch+2

    for (int pix = threadIdx.x; pix < NPIX; pix += 256) {
        int i = pix / FW, j = pix % FW;
        float d = ob[3*NPIX + pix] * 100.0f;     // depth cm (inputs never 0)
        float X = ((float)j - 79.5f) * d / f_cam + 250.0f;
        float Z = ((float)(FH-1-i) - 59.5f) * d / f_cam + 88.0f;
        float pos0 = X / 5.0f;
        float pos1 = d / 5.0f;
        float pos2 = Z / 5.0f + 8.0f;

        float fl0 = floorf(pos0), fl1 = floorf(pos1), fl2 = floorf(pos2);
        float p0f[2] = {fl0, fl0+1.0f}, p1f[2] = {fl1, fl1+1.0f};
        float w0[2], w1[2];
        #pragma unroll
        for (int k = 0; k < 2; k++) {
            w0[k] = (1.0f - fabsf(pos0 - p0f[k])) * ((p0f[k] > 0.0f && p0f[k] < 100.0f) ? 1.0f : 0.0f);
            w1[k] = (1.0f - fabsf(pos1 - p1f[k])) * ((p1f[k] > 0.0f && p1f[k] < 100.0f) ? 1.0f : 0.0f);
        }
        // z-weight sum: exp channel uses all safe z, agent channels z in [13,25)
        float wz = 0.0f;
        #pragma unroll
        for (int k = 0; k < 2; k++) {
            float p = fl2 + (float)k;
            if (p > 0.0f && p < 80.0f) {
                float w = 1.0f - fabsf(pos2 - p);
                if (ch == 0) wz += w;
                else { int zi = (int)p; if (zi >= 13 && zi < 25) wz += w; }
            }
        }
        if (wz <= 0.0f) continue;
        if (w0[0] == 0.0f && w0[1] == 0.0f) continue;
        if (w1[0] == 0.0f && w1[1] == 0.0f) continue;

        float wf = (ch >= 2) ? wz * fsrc[pix] : wz;   // ch 0,1 have feature==1
        #pragma unroll
        for (int a = 0; a < 2; a++) {
            if (w0[a] == 0.0f) continue;
            int ix = (int)p0f[a];
            #pragma unroll
            for (int c = 0; c < 2; c++) {
                if (w1[c] == 0.0f) continue;
                int iy = (int)p1f[c];
                atomicAdd(&acc[iy*VRD + ix], w0[a]*w1[c]*wf);
            }
        }
    }
    __syncthreads();
    float* dst = g_hp + ((size_t)b*TCH + ch)*CELLS;
    for (int i = threadIdx.x; i < CELLS; i += 256) dst[i] = acc[i];
}

// rotation grid_sample over compact bbox-local thread grid; clip fused into tap reads
__global__ void k_rotate(const float* __restrict__ poses) {
    int b  = blockIdx.y;
    int t  = blockIdx.x*blockDim.x + threadIdx.x;
    int i0 = g_bbox[b][0], i1 = g_bbox[b][1], j0 = g_bbox[b][2], j1 = g_bbox[b][3];
    int w  = j1 - j0 + 1, h = i1 - i0 + 1;
    int li = t / w, lj = t % w;
    if (li >= h) return;
    int r = i0 + li, col = j0 + lj;

    float th = (90.0f - poses[b*3+2]) * 0.017453292519943295f;
    float ct = cosf(th), st = sinf(th);
    float x = (2.0f*col + 1.0f)/480.0f - 1.0f;
    float y = (2.0f*r   + 1.0f)/480.0f - 1.0f;
    float gx = ct*x - st*y;
    float gy = st*x + ct*y;
    float xs = (gx + 1.0f)*0.5f*479.0f;
    float ys = (gy + 1.0f)*0.5f*479.0f;
    float x0f = floorf(xs), y0f = floorf(ys);

    float acc[TCH];
    #pragma unroll
    for (int c = 0; c < TCH; c++) acc[c] = 0.0f;

    const float* hpb = g_hp + (size_t)b*TCH*CELLS;
    #pragma unroll
    for (int dy = 0; dy < 2; dy++) {
        float pyf = y0f + (float)dy;
        if (!(pyf >= 0.0f && pyf < 480.0f)) continue;
        int yi = (int)pyf;
        if (yi < 240 || yi >= 340) continue;             // agent_view zero outside window
        float wy = dy ? (ys - y0f) : (y0f + 1.0f - ys);
        #pragma unroll
        for (int dx = 0; dx < 2; dx++) {
            float pxf = x0f + (float)dx;
            if (!(pxf >= 0.0f && pxf < 480.0f)) continue;
            int xi = (int)pxf;
            if (xi < 190 || xi >= 290) continue;
            float wx = dx ? (xs - x0f) : (x0f + 1.0f - xs);
            float wgt = wx*wy;
            const float* tp = hpb + (yi-240)*VRD + (xi-190);
            // tile c0 = clip(hp[1]), c1 = clip(hp[0]), c>=2 = clip(hp[c]/5)
            acc[0] += wgt * fminf(tp[CELLS], 1.0f);
            acc[1] += wgt * fminf(tp[0],     1.0f);
            #pragma unroll
            for (int c = 2; c < TCH; c++)
                acc[c] += wgt * fminf(tp[(size_t)c*CELLS] * 0.2f, 1.0f);
        }
    }
    float* rp = g_rot + (size_t)b*TCH*MS2 + (size_t)r*MS + col;
    #pragma unroll
    for (int c = 0; c < TCH; c++) rp[(size_t)c*MS2] = acc[c];
}

// translation grid_sample + max(maps_last) + ch2/ch3 special + agent mask
__global__ void k_final(const float* __restrict__ maps_last,
                        const float* __restrict__ poses,
                        float* __restrict__ out) {
    const int GPR = MS/4;
    int t = blockIdx.x*blockDim.x + threadIdx.x;
    if (t >= NB*MS*GPR) return;
    int b    = t / (MS*GPR);
    int rem  = t % (MS*GPR);
    int r    = rem / GPR;
    int col0 = (rem % GPR)*4;

    float pxp = poses[b*3+0], pyp = poses[b*3+1];
    float stx = -((pxp*100.0f)/5.0f - 240.0f)/240.0f;
    float sty = -((pyp*100.0f)/5.0f - 240.0f)/240.0f;

    float yb  = (2.0f*r + 1.0f)/480.0f - 1.0f + sty;
    float ys  = (yb + 1.0f)*0.5f*479.0f;
    float y0f = floorf(ys);
    float wy0 = (y0f + 1.0f) - ys;
    float wy1 = ys - y0f;
    int   ry0 = (int)y0f, ry1 = ry0 + 1;
    int i0 = g_bbox[b][0], i1 = g_bbox[b][1], j0 = g_bbox[b][2], j1 = g_bbox[b][3];
    bool vy0 = (y0f       >= 0.0f && y0f       < 480.0f) && ry0 >= i0 && ry0 <= i1;
    bool vy1 = (y0f+1.0f  >= 0.0f && y0f+1.0f  < 480.0f) && ry1 >= i0 && ry1 <= i1;
    int ry0c = min(max(ry0,0), MS-1), ry1c = min(max(ry1,0), MS-1);

    float wx0[4], wx1[4]; int cx0[4], cx0c[4]; bool vx0[4], vx1[4];
    bool anyx = false;
    #pragma unroll
    for (int p = 0; p < 4; p++) {
        float xb  = (2.0f*(col0+p) + 1.0f)/480.0f - 1.0f + stx;
        float xs  = (xb + 1.0f)*0.5f*479.0f;
        float x0f = floorf(xs);
        wx0[p] = (x0f + 1.0f) - xs;
        wx1[p] = xs - x0f;
        cx0[p] = (int)x0f;
        vx0[p] = (x0f      >= 0.0f && x0f      < 480.0f) && cx0[p]   >= j0 && cx0[p]   <= j1;
        vx1[p] = (x0f+1.0f >= 0.0f && x0f+1.0f < 480.0f) && cx0[p]+1 >= j0 && cx0[p]+1 <= j1;
        cx0c[p] = min(max(cx0[p],0), MS-2);
        anyx = anyx || vx0[p] || vx1[p];
    }
    bool active = (vy0 || vy1) && anyx;

    int rr = (int)(pyp*100.0f/5.0f);
    int cc = (int)(pxp*100.0f/5.0f);
    bool mrow = (abs(r - rr) <= 1);

    size_t mbase = (size_t)b*NC*MS2 + (size_t)r*MS + col0;
    float4 ml3 = *(const float4*)(maps_last + mbase + 3*(size_t)MS2);

    #pragma unroll
    for (int c = 0; c < NC; c++) {
        float4 o;
        if (c == 2) {
            o = ml3;                                   // map_pred[2] = pre-mask map_pred[3]
        } else if (c == 3) {
            o = ml3;
            if (mrow) {
                if (abs(col0+0 - cc) <= 1) o.x = 1.0f;
                if (abs(col0+1 - cc) <= 1) o.y = 1.0f;
                if (abs(col0+2 - cc) <= 1) o.z = 1.0f;
                if (abs(col0+3 - cc) <= 1) o.w = 1.0f;
            }
        } else {
            float4 m = *(const float4*)(maps_last + mbase + (size_t)c*MS2);
            float tv[4] = {0.0f, 0.0f, 0.0f, 0.0f};
            if (active) {
                int rc = (c < 2) ? c : (c - 2);
                const float* base = g_rot + ((size_t)b*TCH + rc)*MS2;
                const float* row0 = base + (size_t)ry0c*MS;
                const float* row1 = base + (size_t)ry1c*MS;
                #pragma unroll
                for (int p = 0; p < 4; p++) {
                    float acc = 0.0f;
                    if (vy0) {
                        if (vx0[p]) acc += wx0[p]*wy0*row0[cx0c[p]];
                        if (vx1[p]) acc += wx1[p]*wy0*row0[cx0c[p]+1];
                    }
                    if (vy1) {
                        if (vx0[p]) acc += wx0[p]*wy1*row1[cx0c[p]];
                        if (vx1[p]) acc += wx1[p]*wy1*row1[cx0c[p]+1];
                    }
                    tv[p] = acc;
                }
            }
            o.x = fmaxf(m.x, tv[0]);
            o.y = fmaxf(m.y, tv[1]);
            o.z = fmaxf(m.z, tv[2]);
            o.w = fmaxf(m.w, tv[3]);
        }
        *(float4*)(out + mbase + (size_t)c*MS2) = o;
    }
}

extern "C" void kernel_launch(void* const* d_in, const int* in_sizes, int n_in,
                              void* d_out, int out_size) {
    const float* obs       = (const float*)d_in[0];   // (8,20,120,160)
    const float* maps_last = (const float*)d_in[1];   // (8,20,480,480)
    const float* poses     = (const float*)d_in[2];   // (8,3)
    float* out = (float*)d_out;                       // (8,20,480,480)

    float f_cam = (float)((double)FW / 2.0 / tan(79.0/2.0 * 3.14159265358979323846/180.0));

    k_bbox  <<<1, NB>>>(poses);
    k_splat <<<dim3(TCH, NB), 256>>>(obs, f_cam);
    k_rotate<<<dim3((RB*RB + 255)/256, NB), 256>>>(poses);
    k_final <<<(NB*MS*(MS/4) + 255)/256, 256>>>(maps_last, poses, out);
}

// round 3
// speedup vs baseline: 1.2896x; 1.2896x over previous
#include <cuda_runtime.h>
#include <math.h>

#define NB 8
#define FH 120
#define FW 160
#define NPIX (FH*FW)
#define NSEM 16
#define NC 20
#define MS 480
#define MS2 (MS*MS)
#define TCH 18            // hp: 0=exp count, 1=agent count, 2..17=agent sem
#define VRD 100
#define CELLS (VRD*VRD)
#define RB 160            // compact rot tile side (max bbox ~148)
#define RB2 (RB*RB)

// scratch (static device memory: allowed)
__device__ float g_hp[NB*TCH*CELLS];                  // 5.76 MB
__device__ float g_rotc[(size_t)NB*TCH*RB2];          // 14.7 MB compact rotated planes
__device__ int   g_bbox[NB][4];                       // imin, imax, jmin, jmax (inclusive)

__global__ void k_zero() {
    int i = blockIdx.x*blockDim.x + threadIdx.x;
    if (i < NB*TCH*CELLS) g_hp[i] = 0.0f;
}

// analytic bounding box of the rotated window support (conservative)
__global__ void k_bbox(const float* __restrict__ poses) {
    int b = threadIdx.x;
    if (b >= NB) return;
    float th = (90.0f - poses[b*3+2]) * 0.017453292519943295f;
    float ct = cosf(th), st = sinf(th);
    const float gxlo = 189.0f/239.5f - 1.0f, gxhi = 290.0f/239.5f - 1.0f;
    const float gylo = 239.0f/239.5f - 1.0f, gyhi = 340.0f/239.5f - 1.0f;
    float gxs[2] = {gxlo, gxhi}, gys[2] = {gylo, gyhi};
    float xmn = 1e9f, xmx = -1e9f, ymn = 1e9f, ymx = -1e9f;
    #pragma unroll
    for (int a = 0; a < 2; a++)
        #pragma unroll
        for (int c = 0; c < 2; c++) {
            float gx = gxs[a], gy = gys[c];
            float x =  ct*gx + st*gy;
            float y = -st*gx + ct*gy;
            xmn = fminf(xmn, x); xmx = fmaxf(xmx, x);
            ymn = fminf(ymn, y); ymx = fmaxf(ymx, y);
        }
    int jmn = (int)floorf((xmn + 1.0f)*240.0f - 0.5f) - 2;
    int jmx = (int)ceilf ((xmx + 1.0f)*240.0f - 0.5f) + 2;
    int imn = (int)floorf((ymn + 1.0f)*240.0f - 0.5f) - 2;
    int imx = (int)ceilf ((ymx + 1.0f)*240.0f - 0.5f) + 2;
    g_bbox[b][0] = max(imn, 0); g_bbox[b][1] = min(imx, MS-1);
    g_bbox[b][2] = max(jmn, 0); g_bbox[b][3] = min(jmx, MS-1);
}

// one thread per pixel, projection computed once, global spread atomics (REDG)
__global__ void k_splat(const float* __restrict__ obs, float f_cam) {
    int t = blockIdx.x*blockDim.x + threadIdx.x;
    if (t >= NB*NPIX) return;
    int b = t / NPIX, pix = t % NPIX;
    int i = pix / FW, j = pix % FW;
    const float* ob = obs + (size_t)b*NC*NPIX;

    float d = ob[3*NPIX + pix] * 100.0f;               // depth cm (inputs never 0)
    float X = ((float)j - 79.5f) * d / f_cam + 250.0f;
    float Z = ((float)(FH-1-i) - 59.5f) * d / f_cam + 88.0f;
    float pos0 = X / 5.0f;
    float pos1 = d / 5.0f;
    float pos2 = Z / 5.0f + 8.0f;

    float fl0 = floorf(pos0), fl1 = floorf(pos1), fl2 = floorf(pos2);
    float p0f[2] = {fl0, fl0+1.0f}, p1f[2] = {fl1, fl1+1.0f};
    float w0[2], w1[2];
    #pragma unroll
    for (int k = 0; k < 2; k++) {
        w0[k] = (1.0f - fabsf(pos0 - p0f[k])) * ((p0f[k] > 0.0f && p0f[k] < 100.0f) ? 1.0f : 0.0f);
        w1[k] = (1.0f - fabsf(pos1 - p1f[k])) * ((p1f[k] > 0.0f && p1f[k] < 100.0f) ? 1.0f : 0.0f);
    }
    float wze = 0.0f, wza = 0.0f;
    #pragma unroll
    for (int k = 0; k < 2; k++) {
        float p = fl2 + (float)k;
        if (p > 0.0f && p < 80.0f) {
            float wz = 1.0f - fabsf(pos2 - p);
            wze += wz;
            int zi = (int)p;
            if (zi >= 13 && zi < 25) wza += wz;
        }
    }
    if (wze <= 0.0f && wza <= 0.0f) return;
    if (w0[0] == 0.0f && w0[1] == 0.0f) return;
    if (w1[0] == 0.0f && w1[1] == 0.0f) return;

    float sem[NSEM];
    if (wza > 0.0f) {
        #pragma unroll
        for (int s = 0; s < NSEM; s++) sem[s] = ob[(4+s)*NPIX + pix];
    }
    float* hpb = g_hp + (size_t)b*TCH*CELLS;
    #pragma unroll
    for (int a = 0; a < 2; a++) {
        if (w0[a] == 0.0f) continue;
        int ix = (int)p0f[a];
        #pragma unroll
        for (int c2 = 0; c2 < 2; c2++) {
            if (w1[c2] == 0.0f) continue;
            int iy = (int)p1f[c2];
            float wxy = w0[a]*w1[c2];
            int cell = iy*VRD + ix;
            if (wze > 0.0f) atomicAdd(hpb + cell, wxy*wze);
            if (wza > 0.0f) {
                float wag = wxy*wza;
                atomicAdd(hpb + CELLS + cell, wag);
                #pragma unroll
                for (int s = 0; s < NSEM; s++)
                    atomicAdd(hpb + (size_t)(2+s)*CELLS + cell, wag*sem[s]);
            }
        }
    }
}

// rotation grid_sample over compact bbox grid; clip fused; writes bbox-local planes
__global__ void k_rotate(const float* __restrict__ poses) {
    int b  = blockIdx.y;
    int t  = blockIdx.x*blockDim.x + threadIdx.x;
    int i0 = g_bbox[b][0], i1 = g_bbox[b][1], j0 = g_bbox[b][2], j1 = g_bbox[b][3];
    int w  = j1 - j0 + 1, h = i1 - i0 + 1;
    int li = t / w, lj = t % w;
    if (li >= h) return;
    int r = i0 + li, col = j0 + lj;

    float th = (90.0f - poses[b*3+2]) * 0.017453292519943295f;
    float ct = cosf(th), st = sinf(th);
    float x = (2.0f*col + 1.0f)/480.0f - 1.0f;
    float y = (2.0f*r   + 1.0f)/480.0f - 1.0f;
    float gx = ct*x - st*y;
    float gy = st*x + ct*y;
    float xs = (gx + 1.0f)*0.5f*479.0f;
    float ys = (gy + 1.0f)*0.5f*479.0f;
    float x0f = floorf(xs), y0f = floorf(ys);

    float acc[TCH];
    #pragma unroll
    for (int c = 0; c < TCH; c++) acc[c] = 0.0f;

    const float* hpb = g_hp + (size_t)b*TCH*CELLS;
    #pragma unroll
    for (int dy = 0; dy < 2; dy++) {
        float pyf = y0f + (float)dy;
        if (!(pyf >= 0.0f && pyf < 480.0f)) continue;
        int yi = (int)pyf;
        if (yi < 240 || yi >= 340) continue;
        float wy = dy ? (ys - y0f) : (y0f + 1.0f - ys);
        #pragma unroll
        for (int dx = 0; dx < 2; dx++) {
            float pxf = x0f + (float)dx;
            if (!(pxf >= 0.0f && pxf < 480.0f)) continue;
            int xi = (int)pxf;
            if (xi < 190 || xi >= 290) continue;
            float wx = dx ? (xs - x0f) : (x0f + 1.0f - xs);
            float wgt = wx*wy;
            const float* tp = hpb + (yi-240)*VRD + (xi-190);
            acc[0] += wgt * fminf(tp[CELLS], 1.0f);              // fp_map = clip(agent count)
            acc[1] += wgt * fminf(tp[0],     1.0f);              // fp_exp = clip(exp count)
            #pragma unroll
            for (int c = 2; c < TCH; c++)
                acc[c] += wgt * fminf(tp[(size_t)c*CELLS] * 0.2f, 1.0f);
        }
    }
    float* rp = g_rotc + (size_t)b*TCH*RB2 + (size_t)li*RB + lj;
    #pragma unroll
    for (int c = 0; c < TCH; c++) rp[(size_t)c*RB2] = acc[c];
}

// translation grid_sample + max(maps_last) + specials; one thread per (b,c,r,4cols)
__global__ void k_final(const float* __restrict__ maps_last,
                        const float* __restrict__ poses,
                        float* __restrict__ out) {
    const int GPR = MS/4;   // 120
    int t = blockIdx.x*blockDim.x + threadIdx.x;
    if (t >= NB*NC*MS*GPR) return;
    int g    = t % GPR;
    int r    = (t / GPR) % MS;
    int c    = (t / (GPR*MS)) % NC;
    int b    =  t / (GPR*MS*NC);
    int col0 = g*4;

    size_t mbase = ((size_t)b*NC + c)*MS2 + (size_t)r*MS + col0;

    float pxp = poses[b*3+0], pyp = poses[b*3+1];

    if (c == 2 || c == 3) {
        // both come from maps_last channel 3 (translated ch2/ch3 are zero)
        size_t m3 = ((size_t)b*NC + 3)*MS2 + (size_t)r*MS + col0;
        float4 o = *(const float4*)(maps_last + m3);
        if (c == 3) {
            int rr = (int)(pyp*100.0f/5.0f);
            int cc = (int)(pxp*100.0f/5.0f);
            if (abs(r - rr) <= 1) {
                if (abs(col0+0 - cc) <= 1) o.x = 1.0f;
                if (abs(col0+1 - cc) <= 1) o.y = 1.0f;
                if (abs(col0+2 - cc) <= 1) o.z = 1.0f;
                if (abs(col0+3 - cc) <= 1) o.w = 1.0f;
            }
        }
        *(float4*)(out + mbase) = o;
        return;
    }

    float4 m = *(const float4*)(maps_last + mbase);

    float stx = -((pxp*100.0f)/5.0f - 240.0f)/240.0f;
    float sty = -((pyp*100.0f)/5.0f - 240.0f)/240.0f;

    float yb  = (2.0f*r + 1.0f)/480.0f - 1.0f + sty;
    float ys  = (yb + 1.0f)*0.5f*479.0f;
    float y0f = floorf(ys);
    float wy0 = (y0f + 1.0f) - ys;
    float wy1 = ys - y0f;
    int   ry0 = (int)y0f, ry1 = ry0 + 1;
    int i0 = g_bbox[b][0], i1 = g_bbox[b][1], j0 = g_bbox[b][2], j1 = g_bbox[b][3];
    bool vy0 = (y0f      >= 0.0f && y0f      < 480.0f) && ry0 >= i0 && ry0 <= i1;
    bool vy1 = (y0f+1.0f >= 0.0f && y0f+1.0f < 480.0f) && ry1 >= i0 && ry1 <= i1;

    float tv[4] = {0.0f, 0.0f, 0.0f, 0.0f};
    if (vy0 || vy1) {
        int rc = (c < 2) ? c : (c - 2);
        const float* base = g_rotc + ((size_t)b*TCH + rc)*RB2;
        // local row indices (clamped only for inactive-pointer safety)
        int ly0 = min(max(ry0 - i0, 0), RB-1);
        int ly1 = min(max(ry1 - i0, 0), RB-1);
        const float* row0 = base + (size_t)ly0*RB;
        const float* row1 = base + (size_t)ly1*RB;
        #pragma unroll
        for (int p = 0; p < 4; p++) {
            float xb  = (2.0f*(col0+p) + 1.0f)/480.0f - 1.0f + stx;
            float xs  = (xb + 1.0f)*0.5f*479.0f;
            float x0f = floorf(xs);
            float wx0 = (x0f + 1.0f) - xs;
            float wx1 = xs - x0f;
            int   cx0 = (int)x0f;
            bool vx0 = (x0f      >= 0.0f && x0f      < 480.0f) && cx0   >= j0 && cx0   <= j1;
            bool vx1 = (x0f+1.0f >= 0.0f && x0f+1.0f < 480.0f) && cx0+1 >= j0 && cx0+1 <= j1;
            if (!(vx0 || vx1)) continue;
            int lx0 = min(max(cx0 - j0, 0), RB-2);
            float acc = 0.0f;
            if (vy0) {
                if (vx0) acc += wx0*wy0*row0[lx0];
                if (vx1) acc += wx1*wy0*row0[lx0+1];
            }
            if (vy1) {
                if (vx0) acc += wx0*wy1*row1[lx0];
                if (vx1) acc += wx1*wy1*row1[lx0+1];
            }
            tv[p] = acc;
        }
    }
    float4 o;
    o.x = fmaxf(m.x, tv[0]);
    o.y = fmaxf(m.y, tv[1]);
    o.z = fmaxf(m.z, tv[2]);
    o.w = fmaxf(m.w, tv[3]);
    *(float4*)(out + mbase) = o;
}

extern "C" void kernel_launch(void* const* d_in, const int* in_sizes, int n_in,
                              void* d_out, int out_size) {
    const float* obs       = (const float*)d_in[0];   // (8,20,120,160)
    const float* maps_last = (const float*)d_in[1];   // (8,20,480,480)
    const float* poses     = (const float*)d_in[2];   // (8,3)
    float* out = (float*)d_out;                       // (8,20,480,480)

    float f_cam = (float)((double)FW / 2.0 / tan(79.0/2.0 * 3.14159265358979323846/180.0));

    k_zero  <<<(NB*TCH*CELLS + 255)/256, 256>>>();
    k_bbox  <<<1, NB>>>(poses);
    k_splat <<<(NB*NPIX + 255)/256, 256>>>(obs, f_cam);
    k_rotate<<<dim3((RB*RB + 255)/256, NB), 256>>>(poses);
    k_final <<<(NB*NC*MS*(MS/4) + 255)/256, 256>>>(maps_last, poses, out);
}

// round 4
// speedup vs baseline: 1.6916x; 1.3118x over previous
#include <cuda_runtime.h>
#include <math.h>

#define NB 8
#define FH 120
#define FW 160
#define NPIX (FH*FW)
#define NSEM 16
#define NC 20
#define MS 480
#define MS2 (MS*MS)
#define TCH 18            // tile channels: 0=fp_map, 1=fp_exp, 2..17=sem
#define HPC 20            // padded interleaved hp channels (5 x float4)
#define VRD 100
#define CELLS (VRD*VRD)
#define RB 160            // compact rot tile side (max bbox ~148)
#define RB2 (RB*RB)

// scratch (static device memory: allowed)
// hp layout: [b][cell][20]: ch0=exp count, ch1=agent count, ch2..17=agent sem, 18/19 pad
__device__ float4 g_hp4[(size_t)NB*CELLS*5];          // 6.4 MB, L2-resident
__device__ float  g_rotc[(size_t)NB*TCH*RB2];         // 14.7 MB compact rotated planes
__device__ int    g_bbox[NB][4];                      // imin, imax, jmin, jmax (inclusive)

__device__ __forceinline__ void red_v4(float* p, float a, float b, float c, float d) {
    asm volatile("red.global.add.v4.f32 [%0], {%1, %2, %3, %4};"
                 :: "l"(p), "f"(a), "f"(b), "f"(c), "f"(d) : "memory");
}

__global__ void k_zero() {
    size_t i = blockIdx.x*(size_t)blockDim.x + threadIdx.x;
    if (i < (size_t)NB*CELLS*5) g_hp4[i] = make_float4(0.f, 0.f, 0.f, 0.f);
}

// analytic bounding box of the rotated window support (conservative)
__global__ void k_bbox(const float* __restrict__ poses) {
    int b = threadIdx.x;
    if (b >= NB) return;
    float th = (90.0f - poses[b*3+2]) * 0.017453292519943295f;
    float ct = cosf(th), st = sinf(th);
    const float gxlo = 189.0f/239.5f - 1.0f, gxhi = 290.0f/239.5f - 1.0f;
    const float gylo = 239.0f/239.5f - 1.0f, gyhi = 340.0f/239.5f - 1.0f;
    float gxs[2] = {gxlo, gxhi}, gys[2] = {gylo, gyhi};
    float xmn = 1e9f, xmx = -1e9f, ymn = 1e9f, ymx = -1e9f;
    #pragma unroll
    for (int a = 0; a < 2; a++)
        #pragma unroll
        for (int c = 0; c < 2; c++) {
            float gx = gxs[a], gy = gys[c];
            float x =  ct*gx + st*gy;
            float y = -st*gx + ct*gy;
            xmn = fminf(xmn, x); xmx = fmaxf(xmx, x);
            ymn = fminf(ymn, y); ymx = fmaxf(ymx, y);
        }
    int jmn = (int)floorf((xmn + 1.0f)*240.0f - 0.5f) - 2;
    int jmx = (int)ceilf ((xmx + 1.0f)*240.0f - 0.5f) + 2;
    int imn = (int)floorf((ymn + 1.0f)*240.0f - 0.5f) - 2;
    int imx = (int)ceilf ((ymx + 1.0f)*240.0f - 0.5f) + 2;
    g_bbox[b][0] = max(imn, 0); g_bbox[b][1] = min(imx, MS-1);
    g_bbox[b][2] = max(jmn, 0); g_bbox[b][3] = min(jmx, MS-1);
}

// one thread per pixel; vector reductions into interleaved hp
__global__ void k_splat(const float* __restrict__ obs, float f_cam) {
    int t = blockIdx.x*blockDim.x + threadIdx.x;
    if (t >= NB*NPIX) return;
    int b = t / NPIX, pix = t % NPIX;
    int i = pix / FW, j = pix % FW;
    const float* ob = obs + (size_t)b*NC*NPIX;

    float d = ob[3*NPIX + pix] * 100.0f;               // depth cm (inputs never 0)
    float X = ((float)j - 79.5f) * d / f_cam + 250.0f;
    float Z = ((float)(FH-1-i) - 59.5f) * d / f_cam + 88.0f;
    float pos0 = X / 5.0f;
    float pos1 = d / 5.0f;
    float pos2 = Z / 5.0f + 8.0f;

    float fl0 = floorf(pos0), fl1 = floorf(pos1), fl2 = floorf(pos2);
    float p0f[2] = {fl0, fl0+1.0f}, p1f[2] = {fl1, fl1+1.0f};
    float w0[2], w1[2];
    #pragma unroll
    for (int k = 0; k < 2; k++) {
        w0[k] = (1.0f - fabsf(pos0 - p0f[k])) * ((p0f[k] > 0.0f && p0f[k] < 100.0f) ? 1.0f : 0.0f);
        w1[k] = (1.0f - fabsf(pos1 - p1f[k])) * ((p1f[k] > 0.0f && p1f[k] < 100.0f) ? 1.0f : 0.0f);
    }
    float wze = 0.0f, wza = 0.0f;
    #pragma unroll
    for (int k = 0; k < 2; k++) {
        float p = fl2 + (float)k;
        if (p > 0.0f && p < 80.0f) {
            float wz = 1.0f - fabsf(pos2 - p);
            wze += wz;
            int zi = (int)p;
            if (zi >= 13 && zi < 25) wza += wz;
        }
    }
    if (wze <= 0.0f && wza <= 0.0f) return;
    if (w0[0] == 0.0f && w0[1] == 0.0f) return;
    if (w1[0] == 0.0f && w1[1] == 0.0f) return;

    bool agent = (wza > 0.0f);
    float sem[NSEM];
    #pragma unroll
    for (int s = 0; s < NSEM; s++) sem[s] = 0.0f;
    if (agent) {
        #pragma unroll
        for (int s = 0; s < NSEM; s++) sem[s] = ob[(4+s)*NPIX + pix];
    }

    float* hpb = (float*)(g_hp4 + (size_t)b*CELLS*5);
    #pragma unroll
    for (int a = 0; a < 2; a++) {
        if (w0[a] == 0.0f) continue;
        int ix = (int)p0f[a];
        #pragma unroll
        for (int c2 = 0; c2 < 2; c2++) {
            if (w1[c2] == 0.0f) continue;
            int iy = (int)p1f[c2];
            float wxy = w0[a]*w1[c2];
            float wag = wxy*wza;
            float* cp = hpb + (size_t)(iy*VRD + ix)*HPC;
            red_v4(cp, wxy*wze, wag, wag*sem[0], wag*sem[1]);
            if (agent) {
                red_v4(cp+4,  wag*sem[2],  wag*sem[3],  wag*sem[4],  wag*sem[5]);
                red_v4(cp+8,  wag*sem[6],  wag*sem[7],  wag*sem[8],  wag*sem[9]);
                red_v4(cp+12, wag*sem[10], wag*sem[11], wag*sem[12], wag*sem[13]);
                red_v4(cp+16, wag*sem[14], wag*sem[15], 0.0f, 0.0f);
            }
        }
    }
}

// rotation grid_sample over compact bbox grid; vectorized interleaved hp reads; clip fused
__global__ void k_rotate(const float* __restrict__ poses) {
    int b  = blockIdx.y;
    int t  = blockIdx.x*blockDim.x + threadIdx.x;
    int i0 = g_bbox[b][0], i1 = g_bbox[b][1], j0 = g_bbox[b][2], j1 = g_bbox[b][3];
    int w  = j1 - j0 + 1, h = i1 - i0 + 1;
    int li = t / w, lj = t % w;
    if (li >= h) return;
    int r = i0 + li, col = j0 + lj;

    float th = (90.0f - poses[b*3+2]) * 0.017453292519943295f;
    float ct = cosf(th), st = sinf(th);
    float x = (2.0f*col + 1.0f)/480.0f - 1.0f;
    float y = (2.0f*r   + 1.0f)/480.0f - 1.0f;
    float gx = ct*x - st*y;
    float gy = st*x + ct*y;
    float xs = (gx + 1.0f)*0.5f*479.0f;
    float ys = (gy + 1.0f)*0.5f*479.0f;
    float x0f = floorf(xs), y0f = floorf(ys);

    float acc[TCH];
    #pragma unroll
    for (int c = 0; c < TCH; c++) acc[c] = 0.0f;

    const float4* hpb = g_hp4 + (size_t)b*CELLS*5;
    #pragma unroll
    for (int dy = 0; dy < 2; dy++) {
        float pyf = y0f + (float)dy;
        if (!(pyf >= 0.0f && pyf < 480.0f)) continue;
        int yi = (int)pyf;
        if (yi < 240 || yi >= 340) continue;
        float wy = dy ? (ys - y0f) : (y0f + 1.0f - ys);
        #pragma unroll
        for (int dx = 0; dx < 2; dx++) {
            float pxf = x0f + (float)dx;
            if (!(pxf >= 0.0f && pxf < 480.0f)) continue;
            int xi = (int)pxf;
            if (xi < 190 || xi >= 290) continue;
            float wgt = (dx ? (xs - x0f) : (x0f + 1.0f - xs)) * wy;
            const float4* cp = hpb + (size_t)((yi-240)*VRD + (xi-190))*5;
            float4 t0 = cp[0], t1 = cp[1], t2 = cp[2], t3 = cp[3], t4 = cp[4];
            acc[0]  += wgt * fminf(t0.y, 1.0f);            // fp_map = clip(agent count)
            acc[1]  += wgt * fminf(t0.x, 1.0f);            // fp_exp = clip(exp count)
            acc[2]  += wgt * fminf(t0.z*0.2f, 1.0f);
            acc[3]  += wgt * fminf(t0.w*0.2f, 1.0f);
            acc[4]  += wgt * fminf(t1.x*0.2f, 1.0f);
            acc[5]  += wgt * fminf(t1.y*0.2f, 1.0f);
            acc[6]  += wgt * fminf(t1.z*0.2f, 1.0f);
            acc[7]  += wgt * fminf(t1.w*0.2f, 1.0f);
            acc[8]  += wgt * fminf(t2.x*0.2f, 1.0f);
            acc[9]  += wgt * fminf(t2.y*0.2f, 1.0f);
            acc[10] += wgt * fminf(t2.z*0.2f, 1.0f);
            acc[11] += wgt * fminf(t2.w*0.2f, 1.0f);
            acc[12] += wgt * fminf(t3.x*0.2f, 1.0f);
            acc[13] += wgt * fminf(t3.y*0.2f, 1.0f);
            acc[14] += wgt * fminf(t3.z*0.2f, 1.0f);
            acc[15] += wgt * fminf(t3.w*0.2f, 1.0f);
            acc[16] += wgt * fminf(t4.x*0.2f, 1.0f);
            acc[17] += wgt * fminf(t4.y*0.2f, 1.0f);
        }
    }
    float* rp = g_rotc + (size_t)b*TCH*RB2 + (size_t)li*RB + lj;
    #pragma unroll
    for (int c = 0; c < TCH; c++) rp[(size_t)c*RB2] = acc[c];
}

// translation grid_sample + max(maps_last) + specials; one thread per (b,c,r,4cols)
__global__ void k_final(const float* __restrict__ maps_last,
                        const float* __restrict__ poses,
                        float* __restrict__ out) {
    const int GPR = MS/4;   // 120
    int t = blockIdx.x*blockDim.x + threadIdx.x;
    if (t >= NB*NC*MS*GPR) return;
    int g    = t % GPR;
    int r    = (t / GPR) % MS;
    int c    = (t / (GPR*MS)) % NC;
    int b    =  t / (GPR*MS*NC);
    int col0 = g*4;

    size_t mbase = ((size_t)b*NC + c)*MS2 + (size_t)r*MS + col0;

    float pxp = poses[b*3+0], pyp = poses[b*3+1];

    if (c == 2 || c == 3) {
        size_t m3 = ((size_t)b*NC + 3)*MS2 + (size_t)r*MS + col0;
        float4 o = *(const float4*)(maps_last + m3);
        if (c == 3) {
            int rr = (int)(pyp*100.0f/5.0f);
            int cc = (int)(pxp*100.0f/5.0f);
            if (abs(r - rr) <= 1) {
                if (abs(col0+0 - cc) <= 1) o.x = 1.0f;
                if (abs(col0+1 - cc) <= 1) o.y = 1.0f;
                if (abs(col0+2 - cc) <= 1) o.z = 1.0f;
                if (abs(col0+3 - cc) <= 1) o.w = 1.0f;
            }
        }
        *(float4*)(out + mbase) = o;
        return;
    }

    float4 m = *(const float4*)(maps_last + mbase);

    float stx = -((pxp*100.0f)/5.0f - 240.0f)/240.0f;
    float sty = -((pyp*100.0f)/5.0f - 240.0f)/240.0f;

    float yb  = (2.0f*r + 1.0f)/480.0f - 1.0f + sty;
    float ys  = (yb + 1.0f)*0.5f*479.0f;
    float y0f = floorf(ys);
    float wy0 = (y0f + 1.0f) - ys;
    float wy1 = ys - y0f;
    int   ry0 = (int)y0f, ry1 = ry0 + 1;
    int i0 = g_bbox[b][0], i1 = g_bbox[b][1], j0 = g_bbox[b][2], j1 = g_bbox[b][3];
    bool vy0 = (y0f      >= 0.0f && y0f      < 480.0f) && ry0 >= i0 && ry0 <= i1;
    bool vy1 = (y0f+1.0f >= 0.0f && y0f+1.0f < 480.0f) && ry1 >= i0 && ry1 <= i1;

    float tv[4] = {0.0f, 0.0f, 0.0f, 0.0f};
    if (vy0 || vy1) {
        int rc = (c < 2) ? c : (c - 2);
        const float* base = g_rotc + ((size_t)b*TCH + rc)*RB2;
        int ly0 = min(max(ry0 - i0, 0), RB-1);
        int ly1 = min(max(ry1 - i0, 0), RB-1);
        const float* row0 = base + (size_t)ly0*RB;
        const float* row1 = base + (size_t)ly1*RB;
        #pragma unroll
        for (int p = 0; p < 4; p++) {
            float xb  = (2.0f*(col0+p) + 1.0f)/480.0f - 1.0f + stx;
            float xs  = (xb + 1.0f)*0.5f*479.0f;
            float x0f = floorf(xs);
            float wx0 = (x0f + 1.0f) - xs;
            float wx1 = xs - x0f;
            int   cx0 = (int)x0f;
            bool vx0 = (x0f      >= 0.0f && x0f      < 480.0f) && cx0   >= j0 && cx0   <= j1;
            bool vx1 = (x0f+1.0f >= 0.0f && x0f+1.0f < 480.0f) && cx0+1 >= j0 && cx0+1 <= j1;
            if (!(vx0 || vx1)) continue;
            int lx0 = min(max(cx0 - j0, 0), RB-2);
            float acc = 0.0f;
            if (vy0) {
                if (vx0) acc += wx0*wy0*row0[lx0];
                if (vx1) acc += wx1*wy0*row0[lx0+1];
            }
            if (vy1) {
                if (vx0) acc += wx0*wy1*row1[lx0];
                if (vx1) acc += wx1*wy1*row1[lx0+1];
            }
            tv[p] = acc;
        }
    }
    float4 o;
    o.x = fmaxf(m.x, tv[0]);
    o.y = fmaxf(m.y, tv[1]);
    o.z = fmaxf(m.z, tv[2]);
    o.w = fmaxf(m.w, tv[3]);
    *(float4*)(out + mbase) = o;
}

extern "C" void kernel_launch(void* const* d_in, const int* in_sizes, int n_in,
                              void* d_out, int out_size) {
    const float* obs       = (const float*)d_in[0];   // (8,20,120,160)
    const float* maps_last = (const float*)d_in[1];   // (8,20,480,480)
    const float* poses     = (const float*)d_in[2];   // (8,3)
    float* out = (float*)d_out;                       // (8,20,480,480)

    float f_cam = (float)((double)FW / 2.0 / tan(79.0/2.0 * 3.14159265358979323846/180.0));

    k_zero  <<<((NB*CELLS*5) + 255)/256, 256>>>();
    k_bbox  <<<1, NB>>>(poses);
    k_splat <<<(NB*NPIX + 255)/256, 256>>>(obs, f_cam);
    k_rotate<<<dim3((RB*RB + 255)/256, NB), 256>>>(poses);
    k_final <<<(NB*NC*MS*(MS/4) + 255)/256, 256>>>(maps_last, poses, out);
}

// round 5
// speedup vs baseline: 2.1470x; 1.2692x over previous
#include <cuda_runtime.h>
#include <math.h>

#define NB 8
#define FH 120
#define FW 160
#define NPIX (FH*FW)
#define NSEM 16
#define NC 20
#define MS 480
#define MS2 (MS*MS)
#define TCH 18            // tile channels: 0=fp_map, 1=fp_exp, 2..17=sem
#define HPC 20            // padded interleaved hp channels (5 x float4)
#define VRD 100
#define CELLS (VRD*VRD)
#define RB 160            // compact rot tile side (max bbox ~148)
#define RB2 (RB*RB)

// scratch (static device memory: allowed)
// hp layout: [b][cell][20]: f0=exp count, f1=agent count, f2..17=agent sem, 18/19 pad
__device__ float4 g_hp4[(size_t)NB*CELLS*5];          // 6.4 MB, L2-resident
__device__ float  g_rotc[(size_t)NB*TCH*RB2];         // 14.7 MB compact rotated planes
__device__ int    g_bbox[NB][4];                      // imin, imax, jmin, jmax (inclusive)

__device__ __forceinline__ void red_v4(float* p, float a, float b, float c, float d) {
    asm volatile("red.global.add.v4.f32 [%0], {%1, %2, %3, %4};"
                 :: "l"(p), "f"(a), "f"(b), "f"(c), "f"(d) : "memory");
}

// bbox (8 threads of block 0) + zero g_hp4 (all threads)
__global__ void k_bbox_zero(const float* __restrict__ poses) {
    size_t i = blockIdx.x*(size_t)blockDim.x + threadIdx.x;
    if (i < (size_t)NB*CELLS*5) g_hp4[i] = make_float4(0.f, 0.f, 0.f, 0.f);
    if (blockIdx.x != 0 || threadIdx.x >= NB) return;
    int b = threadIdx.x;
    float th = (90.0f - poses[b*3+2]) * 0.017453292519943295f;
    float ct = cosf(th), st = sinf(th);
    const float gxlo = 189.0f/239.5f - 1.0f, gxhi = 290.0f/239.5f - 1.0f;
    const float gylo = 239.0f/239.5f - 1.0f, gyhi = 340.0f/239.5f - 1.0f;
    float gxs[2] = {gxlo, gxhi}, gys[2] = {gylo, gyhi};
    float xmn = 1e9f, xmx = -1e9f, ymn = 1e9f, ymx = -1e9f;
    #pragma unroll
    for (int a = 0; a < 2; a++)
        #pragma unroll
        for (int c = 0; c < 2; c++) {
            float gx = gxs[a], gy = gys[c];
            float x =  ct*gx + st*gy;
            float y = -st*gx + ct*gy;
            xmn = fminf(xmn, x); xmx = fmaxf(xmx, x);
            ymn = fminf(ymn, y); ymx = fmaxf(ymx, y);
        }
    int jmn = (int)floorf((xmn + 1.0f)*240.0f - 0.5f) - 2;
    int jmx = (int)ceilf ((xmx + 1.0f)*240.0f - 0.5f) + 2;
    int imn = (int)floorf((ymn + 1.0f)*240.0f - 0.5f) - 2;
    int imx = (int)ceilf ((ymx + 1.0f)*240.0f - 0.5f) + 2;
    g_bbox[b][0] = max(imn, 0); g_bbox[b][1] = min(imx, MS-1);
    g_bbox[b][2] = max(jmn, 0); g_bbox[b][3] = min(jmx, MS-1);
}

// one thread per pixel; vector reductions into interleaved hp
__global__ void k_splat(const float* __restrict__ obs, float f_cam) {
    int t = blockIdx.x*blockDim.x + threadIdx.x;
    if (t >= NB*NPIX) return;
    int b = t / NPIX, pix = t % NPIX;
    int i = pix / FW, j = pix % FW;
    const float* ob = obs + (size_t)b*NC*NPIX;

    float d = ob[3*NPIX + pix] * 100.0f;               // depth cm (inputs never 0)
    float X = ((float)j - 79.5f) * d / f_cam + 250.0f;
    float Z = ((float)(FH-1-i) - 59.5f) * d / f_cam + 88.0f;
    float pos0 = X / 5.0f;
    float pos1 = d / 5.0f;
    float pos2 = Z / 5.0f + 8.0f;

    float fl0 = floorf(pos0), fl1 = floorf(pos1), fl2 = floorf(pos2);
    float p0f[2] = {fl0, fl0+1.0f}, p1f[2] = {fl1, fl1+1.0f};
    float w0[2], w1[2];
    #pragma unroll
    for (int k = 0; k < 2; k++) {
        w0[k] = (1.0f - fabsf(pos0 - p0f[k])) * ((p0f[k] > 0.0f && p0f[k] < 100.0f) ? 1.0f : 0.0f);
        w1[k] = (1.0f - fabsf(pos1 - p1f[k])) * ((p1f[k] > 0.0f && p1f[k] < 100.0f) ? 1.0f : 0.0f);
    }
    float wze = 0.0f, wza = 0.0f;
    #pragma unroll
    for (int k = 0; k < 2; k++) {
        float p = fl2 + (float)k;
        if (p > 0.0f && p < 80.0f) {
            float wz = 1.0f - fabsf(pos2 - p);
            wze += wz;
            int zi = (int)p;
            if (zi >= 13 && zi < 25) wza += wz;
        }
    }
    if (wze <= 0.0f && wza <= 0.0f) return;
    if (w0[0] == 0.0f && w0[1] == 0.0f) return;
    if (w1[0] == 0.0f && w1[1] == 0.0f) return;

    bool agent = (wza > 0.0f);
    float sem[NSEM];
    #pragma unroll
    for (int s = 0; s < NSEM; s++) sem[s] = 0.0f;
    if (agent) {
        #pragma unroll
        for (int s = 0; s < NSEM; s++) sem[s] = ob[(4+s)*NPIX + pix];
    }

    float* hpb = (float*)(g_hp4 + (size_t)b*CELLS*5);
    #pragma unroll
    for (int a = 0; a < 2; a++) {
        if (w0[a] == 0.0f) continue;
        int ix = (int)p0f[a];
        #pragma unroll
        for (int c2 = 0; c2 < 2; c2++) {
            if (w1[c2] == 0.0f) continue;
            int iy = (int)p1f[c2];
            float wxy = w0[a]*w1[c2];
            float wag = wxy*wza;
            float* cp = hpb + (size_t)(iy*VRD + ix)*HPC;
            red_v4(cp, wxy*wze, wag, wag*sem[0], wag*sem[1]);
            if (agent) {
                red_v4(cp+4,  wag*sem[2],  wag*sem[3],  wag*sem[4],  wag*sem[5]);
                red_v4(cp+8,  wag*sem[6],  wag*sem[7],  wag*sem[8],  wag*sem[9]);
                red_v4(cp+12, wag*sem[10], wag*sem[11], wag*sem[12], wag*sem[13]);
                red_v4(cp+16, wag*sem[14], wag*sem[15], 0.0f, 0.0f);
            }
        }
    }
}

// rotation grid_sample; blockIdx.z picks channel group (0: tile 0..8, 1: tile 9..17)
__global__ void k_rotate(const float* __restrict__ poses) {
    int b  = blockIdx.y;
    int grp = blockIdx.z;
    int t  = blockIdx.x*blockDim.x + threadIdx.x;
    int i0 = g_bbox[b][0], i1 = g_bbox[b][1], j0 = g_bbox[b][2], j1 = g_bbox[b][3];
    int w  = j1 - j0 + 1, h = i1 - i0 + 1;
    int li = t / w, lj = t % w;
    if (li >= h) return;
    int r = i0 + li, col = j0 + lj;

    float th = (90.0f - poses[b*3+2]) * 0.017453292519943295f;
    float ct = cosf(th), st = sinf(th);
    float x = (2.0f*col + 1.0f)/480.0f - 1.0f;
    float y = (2.0f*r   + 1.0f)/480.0f - 1.0f;
    float gx = ct*x - st*y;
    float gy = st*x + ct*y;
    float xs = (gx + 1.0f)*0.5f*479.0f;
    float ys = (gy + 1.0f)*0.5f*479.0f;
    float x0f = floorf(xs), y0f = floorf(ys);

    float acc[9];
    #pragma unroll
    for (int c = 0; c < 9; c++) acc[c] = 0.0f;

    const float4* hpb = g_hp4 + (size_t)b*CELLS*5;
    #pragma unroll
    for (int dy = 0; dy < 2; dy++) {
        float pyf = y0f + (float)dy;
        if (!(pyf >= 0.0f && pyf < 480.0f)) continue;
        int yi = (int)pyf;
        if (yi < 240 || yi >= 340) continue;
        float wy = dy ? (ys - y0f) : (y0f + 1.0f - ys);
        #pragma unroll
        for (int dx = 0; dx < 2; dx++) {
            float pxf = x0f + (float)dx;
            if (!(pxf >= 0.0f && pxf < 480.0f)) continue;
            int xi = (int)pxf;
            if (xi < 190 || xi >= 290) continue;
            float wgt = (dx ? (xs - x0f) : (x0f + 1.0f - xs)) * wy;
            const float4* cp = hpb + (size_t)((yi-240)*VRD + (xi-190))*5;
            if (grp == 0) {
                // tile ch 0..8 -> hp floats {1,0,2..10}
                float4 t0 = cp[0], t1 = cp[1], t2 = cp[2];
                acc[0] += wgt * fminf(t0.y, 1.0f);
                acc[1] += wgt * fminf(t0.x, 1.0f);
                acc[2] += wgt * fminf(t0.z*0.2f, 1.0f);
                acc[3] += wgt * fminf(t0.w*0.2f, 1.0f);
                acc[4] += wgt * fminf(t1.x*0.2f, 1.0f);
                acc[5] += wgt * fminf(t1.y*0.2f, 1.0f);
                acc[6] += wgt * fminf(t1.z*0.2f, 1.0f);
                acc[7] += wgt * fminf(t1.w*0.2f, 1.0f);
                acc[8] += wgt * fminf(t2.x*0.2f, 1.0f);
            } else {
                // tile ch 9..17 -> hp floats 11..19 (19 unused pad -> ch17 = hp[19]? no:)
                // tile ch c (>=2) -> hp float c ; ch 9..17 -> hp 9..17? wait ch2..17 -> hp2..17
                float4 t2 = cp[2], t3 = cp[3], t4 = cp[4];
                acc[0] += wgt * fminf(t2.y*0.2f, 1.0f);   // ch9  = hp[9]
                acc[1] += wgt * fminf(t2.z*0.2f, 1.0f);   // ch10 = hp[10]
                acc[2] += wgt * fminf(t2.w*0.2f, 1.0f);   // ch11 = hp[11]
                acc[3] += wgt * fminf(t3.x*0.2f, 1.0f);   // ch12
                acc[4] += wgt * fminf(t3.y*0.2f, 1.0f);   // ch13
                acc[5] += wgt * fminf(t3.z*0.2f, 1.0f);   // ch14
                acc[6] += wgt * fminf(t3.w*0.2f, 1.0f);   // ch15
                acc[7] += wgt * fminf(t4.x*0.2f, 1.0f);   // ch16
                acc[8] += wgt * fminf(t4.y*0.2f, 1.0f);   // ch17
            }
        }
    }
    // NOTE: grp0 covers tile ch 0..8 (hp floats {1,0,2..8}); grp1 covers ch 9..17.
    float* rp = g_rotc + (size_t)b*TCH*RB2 + (size_t)(grp*9)*RB2 + (size_t)li*RB + lj;
    #pragma unroll
    for (int c = 0; c < 9; c++) rp[(size_t)c*RB2] = acc[c];
}

// translation grid_sample + max(maps_last) + specials; one thread per (b,c',r,8cols)
// c' in [0,19): actual channel c = (c'<2) ? c' : c'+1 ; c==3 thread writes ch2 and ch3
__global__ void k_final(const float* __restrict__ maps_last,
                        const float* __restrict__ poses,
                        float* __restrict__ out) {
    const int GPR = MS/8;   // 60 groups of 8 px
    const int NCH = NC-1;   // 19
    int t = blockIdx.x*blockDim.x + threadIdx.x;
    if (t >= NB*NCH*MS*GPR) return;
    int g    = t % GPR;
    int r    = (t / GPR) % MS;
    int cp_  = (t / (GPR*MS)) % NCH;
    int b    =  t / (GPR*MS*NCH);
    int c    = (cp_ < 2) ? cp_ : cp_ + 1;
    int col0 = g*8;

    float pxp = poses[b*3+0], pyp = poses[b*3+1];
    size_t rowoff = (size_t)r*MS + col0;

    if (c == 3) {
        size_t m3 = ((size_t)b*NC + 3)*MS2 + rowoff;
        size_t m2 = ((size_t)b*NC + 2)*MS2 + rowoff;
        float4 a = *(const float4*)(maps_last + m3);
        float4 bv = *(const float4*)(maps_last + m3 + 4);
        // ch2 = pre-mask ch3 value
        *(float4*)(out + m2)     = a;
        *(float4*)(out + m2 + 4) = bv;
        int rr = (int)(pyp*100.0f/5.0f);
        int cc = (int)(pxp*100.0f/5.0f);
        if (abs(r - rr) <= 1) {
            float* oa = &a.x; float* ob = &bv.x;
            #pragma unroll
            for (int p = 0; p < 4; p++) {
                if (abs(col0+p   - cc) <= 1) oa[p] = 1.0f;
                if (abs(col0+4+p - cc) <= 1) ob[p] = 1.0f;
            }
        }
        *(float4*)(out + m3)     = a;
        *(float4*)(out + m3 + 4) = bv;
        return;
    }

    size_t mbase = ((size_t)b*NC + c)*MS2 + rowoff;
    float4 m0 = *(const float4*)(maps_last + mbase);
    float4 m1 = *(const float4*)(maps_last + mbase + 4);

    float stx = -((pxp*100.0f)/5.0f - 240.0f)/240.0f;
    float sty = -((pyp*100.0f)/5.0f - 240.0f)/240.0f;

    float yb  = (2.0f*r + 1.0f)/480.0f - 1.0f + sty;
    float ys  = (yb + 1.0f)*0.5f*479.0f;
    float y0f = floorf(ys);
    float wy0 = (y0f + 1.0f) - ys;
    float wy1 = ys - y0f;
    int   ry0 = (int)y0f, ry1 = ry0 + 1;
    int i0 = g_bbox[b][0], i1 = g_bbox[b][1], j0 = g_bbox[b][2], j1 = g_bbox[b][3];
    bool vy0 = (y0f      >= 0.0f && y0f      < 480.0f) && ry0 >= i0 && ry0 <= i1;
    bool vy1 = (y0f+1.0f >= 0.0f && y0f+1.0f < 480.0f) && ry1 >= i0 && ry1 <= i1;

    float tv[8];
    #pragma unroll
    for (int p = 0; p < 8; p++) tv[p] = 0.0f;
    if (vy0 || vy1) {
        int rc = (c < 2) ? c : (c - 2);
        const float* base = g_rotc + ((size_t)b*TCH + rc)*RB2;
        int ly0 = min(max(ry0 - i0, 0), RB-1);
        int ly1 = min(max(ry1 - i0, 0), RB-1);
        const float* row0 = base + (size_t)ly0*RB;
        const float* row1 = base + (size_t)ly1*RB;
        #pragma unroll
        for (int p = 0; p < 8; p++) {
            float xb  = (2.0f*(col0+p) + 1.0f)/480.0f - 1.0f + stx;
            float xs  = (xb + 1.0f)*0.5f*479.0f;
            float x0f = floorf(xs);
            float wx0 = (x0f + 1.0f) - xs;
            float wx1 = xs - x0f;
            int   cx0 = (int)x0f;
            bool vx0 = (x0f      >= 0.0f && x0f      < 480.0f) && cx0   >= j0 && cx0   <= j1;
            bool vx1 = (x0f+1.0f >= 0.0f && x0f+1.0f < 480.0f) && cx0+1 >= j0 && cx0+1 <= j1;
            if (!(vx0 || vx1)) continue;
            int lx0 = min(max(cx0 - j0, 0), RB-2);
            float acc = 0.0f;
            if (vy0) {
                if (vx0) acc += wx0*wy0*row0[lx0];
                if (vx1) acc += wx1*wy0*row0[lx0+1];
            }
            if (vy1) {
                if (vx0) acc += wx0*wy1*row1[lx0];
                if (vx1) acc += wx1*wy1*row1[lx0+1];
            }
            tv[p] = acc;
        }
    }
    float4 o0, o1;
    o0.x = fmaxf(m0.x, tv[0]); o0.y = fmaxf(m0.y, tv[1]);
    o0.z = fmaxf(m0.z, tv[2]); o0.w = fmaxf(m0.w, tv[3]);
    o1.x = fmaxf(m1.x, tv[4]); o1.y = fmaxf(m1.y, tv[5]);
    o1.z = fmaxf(m1.z, tv[6]); o1.w = fmaxf(m1.w, tv[7]);
    *(float4*)(out + mbase)     = o0;
    *(float4*)(out + mbase + 4) = o1;
}

extern "C" void kernel_launch(void* const* d_in, const int* in_sizes, int n_in,
                              void* d_out, int out_size) {
    const float* obs       = (const float*)d_in[0];   // (8,20,120,160)
    const float* maps_last = (const float*)d_in[1];   // (8,20,480,480)
    const float* poses     = (const float*)d_in[2];   // (8,3)
    float* out = (float*)d_out;                       // (8,20,480,480)

    float f_cam = (float)((double)FW / 2.0 / tan(79.0/2.0 * 3.14159265358979323846/180.0));

    k_bbox_zero<<<((NB*CELLS*5) + 255)/256, 256>>>(poses);
    k_splat    <<<(NB*NPIX + 255)/256, 256>>>(obs, f_cam);
    k_rotate   <<<dim3((RB*RB + 255)/256, NB, 2), 256>>>(poses);
    k_final    <<<(NB*(NC-1)*MS*(MS/8) + 255)/256, 256>>>(maps_last, poses, out);
}

// round 6
// speedup vs baseline: 2.2248x; 1.0362x over previous
#include <cuda_runtime.h>
#include <math.h>

#define NB 8
#define FH 120
#define FW 160
#define NPIX (FH*FW)
#define NSEM 16
#define NC 20
#define MS 480
#define MS2 (MS*MS)
#define TCH 18            // tile channels: 0=fp_map, 1=fp_exp, 2..17=sem
#define HPC 20            // padded interleaved hp channels (5 x float4)
#define VRD 100
#define CELLS (VRD*VRD)
#define RB 160            // compact rot tile side (max bbox ~148)
#define RB2 (RB*RB)

// scratch (static device memory: allowed)
// hp layout: [b][cell][20]: f0=exp count, f1=agent count, f2..17=agent sem, 18/19 pad
__device__ float4 g_hp4[(size_t)NB*CELLS*5];          // 6.4 MB, L2-resident
__device__ float  g_rotc[(size_t)NB*TCH*RB2];         // compact rotated planes
__device__ int    g_bbox[NB][4];                      // imin, imax, jmin, jmax (inclusive)

__device__ __forceinline__ void red_v4(float* p, float a, float b, float c, float d) {
    asm volatile("red.global.add.v4.f32 [%0], {%1, %2, %3, %4};"
                 :: "l"(p), "f"(a), "f"(b), "f"(c), "f"(d) : "memory");
}

// bbox (8 threads of block 0) + zero g_hp4 (all threads)
__global__ void k_bbox_zero(const float* __restrict__ poses) {
    size_t i = blockIdx.x*(size_t)blockDim.x + threadIdx.x;
    if (i < (size_t)NB*CELLS*5) g_hp4[i] = make_float4(0.f, 0.f, 0.f, 0.f);
    if (blockIdx.x != 0 || threadIdx.x >= NB) return;
    int b = threadIdx.x;
    float th = (90.0f - poses[b*3+2]) * 0.017453292519943295f;
    float ct = cosf(th), st = sinf(th);
    const float gxlo = 189.0f/239.5f - 1.0f, gxhi = 290.0f/239.5f - 1.0f;
    const float gylo = 239.0f/239.5f - 1.0f, gyhi = 340.0f/239.5f - 1.0f;
    float gxs[2] = {gxlo, gxhi}, gys[2] = {gylo, gyhi};
    float xmn = 1e9f, xmx = -1e9f, ymn = 1e9f, ymx = -1e9f;
    #pragma unroll
    for (int a = 0; a < 2; a++)
        #pragma unroll
        for (int c = 0; c < 2; c++) {
            float gx = gxs[a], gy = gys[c];
            float x =  ct*gx + st*gy;
            float y = -st*gx + ct*gy;
            xmn = fminf(xmn, x); xmx = fmaxf(xmx, x);
            ymn = fminf(ymn, y); ymx = fmaxf(ymx, y);
        }
    int jmn = (int)floorf((xmn + 1.0f)*240.0f - 0.5f) - 2;
    int jmx = (int)ceilf ((xmx + 1.0f)*240.0f - 0.5f) + 2;
    int imn = (int)floorf((ymn + 1.0f)*240.0f - 0.5f) - 2;
    int imx = (int)ceilf ((ymx + 1.0f)*240.0f - 0.5f) + 2;
    g_bbox[b][0] = max(imn, 0); g_bbox[b][1] = min(imx, MS-1);
    g_bbox[b][2] = max(jmn, 0); g_bbox[b][3] = min(jmx, MS-1);
}

// one thread per pixel; vector reductions into interleaved hp
__global__ void k_splat(const float* __restrict__ obs, float f_cam) {
    int t = blockIdx.x*blockDim.x + threadIdx.x;
    if (t >= NB*NPIX) return;
    int b = t / NPIX, pix = t % NPIX;
    int i = pix / FW, j = pix % FW;
    const float* ob = obs + (size_t)b*NC*NPIX;

    float d = ob[3*NPIX + pix] * 100.0f;               // depth cm (inputs never 0)
    float X = ((float)j - 79.5f) * d / f_cam + 250.0f;
    float Z = ((float)(FH-1-i) - 59.5f) * d / f_cam + 88.0f;
    float pos0 = X / 5.0f;
    float pos1 = d / 5.0f;
    float pos2 = Z / 5.0f + 8.0f;

    float fl0 = floorf(pos0), fl1 = floorf(pos1), fl2 = floorf(pos2);
    float p0f[2] = {fl0, fl0+1.0f}, p1f[2] = {fl1, fl1+1.0f};
    float w0[2], w1[2];
    #pragma unroll
    for (int k = 0; k < 2; k++) {
        w0[k] = (1.0f - fabsf(pos0 - p0f[k])) * ((p0f[k] > 0.0f && p0f[k] < 100.0f) ? 1.0f : 0.0f);
        w1[k] = (1.0f - fabsf(pos1 - p1f[k])) * ((p1f[k] > 0.0f && p1f[k] < 100.0f) ? 1.0f : 0.0f);
    }
    float wze = 0.0f, wza = 0.0f;
    #pragma unroll
    for (int k = 0; k < 2; k++) {
        float p = fl2 + (float)k;
        if (p > 0.0f && p < 80.0f) {
            float wz = 1.0f - fabsf(pos2 - p);
            wze += wz;
            int zi = (int)p;
            if (zi >= 13 && zi < 25) wza += wz;
        }
    }
    if (wze <= 0.0f && wza <= 0.0f) return;
    if (w0[0] == 0.0f && w0[1] == 0.0f) return;
    if (w1[0] == 0.0f && w1[1] == 0.0f) return;

    bool agent = (wza > 0.0f);
    float sem[NSEM];
    #pragma unroll
    for (int s = 0; s < NSEM; s++) sem[s] = 0.0f;
    if (agent) {
        #pragma unroll
        for (int s = 0; s < NSEM; s++) sem[s] = ob[(4+s)*NPIX + pix];
    }

    float* hpb = (float*)(g_hp4 + (size_t)b*CELLS*5);
    #pragma unroll
    for (int a = 0; a < 2; a++) {
        if (w0[a] == 0.0f) continue;
        int ix = (int)p0f[a];
        #pragma unroll
        for (int c2 = 0; c2 < 2; c2++) {
            if (w1[c2] == 0.0f) continue;
            int iy = (int)p1f[c2];
            float wxy = w0[a]*w1[c2];
            float wag = wxy*wza;
            float* cp = hpb + (size_t)(iy*VRD + ix)*HPC;
            red_v4(cp, wxy*wze, wag, wag*sem[0], wag*sem[1]);
            if (agent) {
                red_v4(cp+4,  wag*sem[2],  wag*sem[3],  wag*sem[4],  wag*sem[5]);
                red_v4(cp+8,  wag*sem[6],  wag*sem[7],  wag*sem[8],  wag*sem[9]);
                red_v4(cp+12, wag*sem[10], wag*sem[11], wag*sem[12], wag*sem[13]);
                red_v4(cp+16, wag*sem[14], wag*sem[15], 0.0f, 0.0f);
            }
        }
    }
}

// rotation grid_sample; blockIdx.z picks channel group (0: tile 0..8, 1: tile 9..17)
__global__ void k_rotate(const float* __restrict__ poses) {
    int b  = blockIdx.y;
    int grp = blockIdx.z;
    int t  = blockIdx.x*blockDim.x + threadIdx.x;
    int i0 = g_bbox[b][0], i1 = g_bbox[b][1], j0 = g_bbox[b][2], j1 = g_bbox[b][3];
    int w  = j1 - j0 + 1, h = i1 - i0 + 1;
    int li = t / w, lj = t % w;
    if (li >= h) return;
    int r = i0 + li, col = j0 + lj;

    float th = (90.0f - poses[b*3+2]) * 0.017453292519943295f;
    float ct = cosf(th), st = sinf(th);
    float x = (2.0f*col + 1.0f)/480.0f - 1.0f;
    float y = (2.0f*r   + 1.0f)/480.0f - 1.0f;
    float gx = ct*x - st*y;
    float gy = st*x + ct*y;
    float xs = (gx + 1.0f)*0.5f*479.0f;
    float ys = (gy + 1.0f)*0.5f*479.0f;
    float x0f = floorf(xs), y0f = floorf(ys);

    float acc[9];
    #pragma unroll
    for (int c = 0; c < 9; c++) acc[c] = 0.0f;

    const float4* hpb = g_hp4 + (size_t)b*CELLS*5;
    #pragma unroll
    for (int dy = 0; dy < 2; dy++) {
        float pyf = y0f + (float)dy;
        if (!(pyf >= 0.0f && pyf < 480.0f)) continue;
        int yi = (int)pyf;
        if (yi < 240 || yi >= 340) continue;
        float wy = dy ? (ys - y0f) : (y0f + 1.0f - ys);
        #pragma unroll
        for (int dx = 0; dx < 2; dx++) {
            float pxf = x0f + (float)dx;
            if (!(pxf >= 0.0f && pxf < 480.0f)) continue;
            int xi = (int)pxf;
            if (xi < 190 || xi >= 290) continue;
            float wgt = (dx ? (xs - x0f) : (x0f + 1.0f - xs)) * wy;
            const float4* cp = hpb + (size_t)((yi-240)*VRD + (xi-190))*5;
            if (grp == 0) {
                float4 t0 = cp[0], t1 = cp[1], t2 = cp[2];
                acc[0] += wgt * fminf(t0.y, 1.0f);
                acc[1] += wgt * fminf(t0.x, 1.0f);
                acc[2] += wgt * fminf(t0.z*0.2f, 1.0f);
                acc[3] += wgt * fminf(t0.w*0.2f, 1.0f);
                acc[4] += wgt * fminf(t1.x*0.2f, 1.0f);
                acc[5] += wgt * fminf(t1.y*0.2f, 1.0f);
                acc[6] += wgt * fminf(t1.z*0.2f, 1.0f);
                acc[7] += wgt * fminf(t1.w*0.2f, 1.0f);
                acc[8] += wgt * fminf(t2.x*0.2f, 1.0f);
            } else {
                float4 t2 = cp[2], t3 = cp[3], t4 = cp[4];
                acc[0] += wgt * fminf(t2.y*0.2f, 1.0f);   // ch9
                acc[1] += wgt * fminf(t2.z*0.2f, 1.0f);
                acc[2] += wgt * fminf(t2.w*0.2f, 1.0f);
                acc[3] += wgt * fminf(t3.x*0.2f, 1.0f);
                acc[4] += wgt * fminf(t3.y*0.2f, 1.0f);
                acc[5] += wgt * fminf(t3.z*0.2f, 1.0f);
                acc[6] += wgt * fminf(t3.w*0.2f, 1.0f);
                acc[7] += wgt * fminf(t4.x*0.2f, 1.0f);
                acc[8] += wgt * fminf(t4.y*0.2f, 1.0f);   // ch17
            }
        }
    }
    float* rp = g_rotc + (size_t)b*TCH*RB2 + (size_t)(grp*9)*RB2 + (size_t)li*RB + lj;
    #pragma unroll
    for (int c = 0; c < 9; c++) rp[(size_t)c*RB2] = acc[c];
}

// translation grid_sample + max(maps_last) + specials.
// grid(120, 19, 8), block(64, 4): zero integer divides.
// blockIdx.y = c' in [0,19): channel c = (c'<2) ? c' : c'+1 ; c==3 writes ch2 and ch3.
__global__ void __launch_bounds__(256) k_final(const float* __restrict__ maps_last,
                        const float* __restrict__ poses,
                        float* __restrict__ out) {
    int g = threadIdx.x;                 // col group (8 px each)
    if (g >= 60) return;
    int r   = blockIdx.x*4 + threadIdx.y;
    int cp_ = blockIdx.y;
    int b   = blockIdx.z;
    int c   = (cp_ < 2) ? cp_ : cp_ + 1;
    int col0 = g << 3;

    float pxp = poses[b*3+0], pyp = poses[b*3+1];
    size_t rowoff = (size_t)r*MS + col0;

    if (c == 3) {
        size_t m3 = ((size_t)b*NC + 3)*MS2 + rowoff;
        size_t m2 = ((size_t)b*NC + 2)*MS2 + rowoff;
        float4 a  = *(const float4*)(maps_last + m3);
        float4 bv = *(const float4*)(maps_last + m3 + 4);
        *(float4*)(out + m2)     = a;      // ch2 = pre-mask ch3 value
        *(float4*)(out + m2 + 4) = bv;
        int rr = (int)(pyp*100.0f/5.0f);
        int cc = (int)(pxp*100.0f/5.0f);
        if (abs(r - rr) <= 1) {
            float* oa = &a.x; float* ob = &bv.x;
            #pragma unroll
            for (int p = 0; p < 4; p++) {
                if (abs(col0+p   - cc) <= 1) oa[p] = 1.0f;
                if (abs(col0+4+p - cc) <= 1) ob[p] = 1.0f;
            }
        }
        *(float4*)(out + m3)     = a;
        *(float4*)(out + m3 + 4) = bv;
        return;
    }

    size_t mbase = ((size_t)b*NC + c)*MS2 + rowoff;
    float4 m0 = *(const float4*)(maps_last + mbase);
    float4 m1 = *(const float4*)(maps_last + mbase + 4);

    float stx = -((pxp*100.0f)/5.0f - 240.0f)/240.0f;
    float sty = -((pyp*100.0f)/5.0f - 240.0f)/240.0f;

    // y taps
    float ys  = ((2.0f*r + 1.0f)/480.0f + sty)*0.5f*479.0f;
    float y0f = floorf(ys);
    float wy0 = (y0f + 1.0f) - ys;
    float wy1 = ys - y0f;
    int   ry0 = (int)y0f, ry1 = ry0 + 1;
    int i0 = g_bbox[b][0], i1 = g_bbox[b][1], j0 = g_bbox[b][2], j1 = g_bbox[b][3];
    bool vy0 = (y0f      >= 0.0f && y0f      < 480.0f) && ry0 >= i0 && ry0 <= i1;
    bool vy1 = (y0f+1.0f >= 0.0f && y0f+1.0f < 480.0f) && ry1 >= i0 && ry1 <= i1;

    float tv[8];
    #pragma unroll
    for (int p = 0; p < 8; p++) tv[p] = 0.0f;
    if (vy0 || vy1) {
        int rc = (c < 2) ? c : (c - 2);
        const float* base = g_rotc + ((size_t)b*TCH + rc)*RB2;
        int ly0 = min(max(ry0 - i0, 0), RB-1);
        int ly1 = min(max(ry1 - i0, 0), RB-1);
        const float* row0 = base + (size_t)ly0*RB;
        const float* row1 = base + (size_t)ly1*RB;
        // xs steps by exactly 479/480 per pixel
        const float XSTEP = 479.0f/480.0f;
        float xs_base = ((2.0f*col0 + 1.0f)/480.0f + stx)*0.5f*479.0f;
        #pragma unroll
        for (int p = 0; p < 8; p++) {
            float xs  = fmaf((float)p, XSTEP, xs_base);
            float x0f = floorf(xs);
            float wx1 = xs - x0f;
            float wx0 = 1.0f - wx1;
            int   cx0 = (int)x0f;
            bool vx0 = (x0f      >= 0.0f && x0f      < 480.0f) && cx0   >= j0 && cx0   <= j1;
            bool vx1 = (x0f+1.0f >= 0.0f && x0f+1.0f < 480.0f) && cx0+1 >= j0 && cx0+1 <= j1;
            if (!(vx0 || vx1)) continue;
            int lx0 = min(max(cx0 - j0, 0), RB-2);
            float acc = 0.0f;
            if (vy0) {
                if (vx0) acc += wx0*wy0*row0[lx0];
                if (vx1) acc += wx1*wy0*row0[lx0+1];
            }
            if (vy1) {
                if (vx0) acc += wx0*wy1*row1[lx0];
                if (vx1) acc += wx1*wy1*row1[lx0+1];
            }
            tv[p] = acc;
        }
    }
    float4 o0, o1;
    o0.x = fmaxf(m0.x, tv[0]); o0.y = fmaxf(m0.y, tv[1]);
    o0.z = fmaxf(m0.z, tv[2]); o0.w = fmaxf(m0.w, tv[3]);
    o1.x = fmaxf(m1.x, tv[4]); o1.y = fmaxf(m1.y, tv[5]);
    o1.z = fmaxf(m1.z, tv[6]); o1.w = fmaxf(m1.w, tv[7]);
    *(float4*)(out + mbase)     = o0;
    *(float4*)(out + mbase + 4) = o1;
}

extern "C" void kernel_launch(void* const* d_in, const int* in_sizes, int n_in,
                              void* d_out, int out_size) {
    const float* obs       = (const float*)d_in[0];   // (8,20,120,160)
    const float* maps_last = (const float*)d_in[1];   // (8,20,480,480)
    const float* poses     = (const float*)d_in[2];   // (8,3)
    float* out = (float*)d_out;                       // (8,20,480,480)

    float f_cam = (float)((double)FW / 2.0 / tan(79.0/2.0 * 3.14159265358979323846/180.0));

    k_bbox_zero<<<((NB*CELLS*5) + 255)/256, 256>>>(poses);
    k_splat    <<<(NB*NPIX + 255)/256, 256>>>(obs, f_cam);
    k_rotate   <<<dim3((RB*RB + 255)/256, NB, 2), 256>>>(poses);
    k_final    <<<dim3(MS/4, NC-1, NB), dim3(64, 4)>>>(maps_last, poses, out);
}